// round 17
// baseline (speedup 1.0000x reference)
#include <cuda_runtime.h>

// ---------------- scratch ----------------
__device__ __align__(16) float d_Y0[16 * 16 * 258 * 258];   // (B,16,258,258)
__device__ __align__(16) float d_Y1[16 * 32 * 130 * 130];   // (B,32,130,130)
__device__ float d_blk0[1024];   // [r2][c2][m16][n16]
__device__ float d_blk1[512];    // [g2][m16][n16]
__device__ float d_part[192];
__device__ float d_bscale[2];

typedef unsigned long long u64;

// ---------------- f32x2 helpers ----------------
__device__ __forceinline__ u64 pk2(float a, float b) {
    u64 r;
    asm("mov.b64 %0, {%1, %2};" : "=l"(r) : "r"(__float_as_uint(a)), "r"(__float_as_uint(b)));
    return r;
}
__device__ __forceinline__ u64 dup2(float a) { return pk2(a, a); }
__device__ __forceinline__ void dfma(u64& d, u64 a, u64 b) {
    asm("fma.rn.f32x2 %0, %1, %2, %0;" : "+l"(d) : "l"(a), "l"(b));
}
__device__ __forceinline__ float2 up2(u64 v) {
    unsigned lo, hi;
    asm("mov.b64 {%0, %1}, %2;" : "=r"(lo), "=r"(hi) : "l"(v));
    return make_float2(__uint_as_float(lo), __uint_as_float(hi));
}
__device__ __forceinline__ void ldw8(const u64* p, u64 wr[8]) {
    const ulonglong2* q = (const ulonglong2*)p;
    ulonglong2 a = q[0], b = q[1], c = q[2], d = q[3];
    wr[0] = a.x; wr[1] = a.y; wr[2] = b.x; wr[3] = b.y;
    wr[4] = c.x; wr[5] = c.y; wr[6] = d.x; wr[7] = d.y;
}

// ---------------- P1: partial sum of squares for b0,b1 ----------------
__global__ __launch_bounds__(256) void k_ssq(const float* __restrict__ b0,
                                             const float* __restrict__ b1) {
    __shared__ float red[256];
    int bid = blockIdx.x, t = threadIdx.x;
    const float* src; long base;
    if (bid < 128) { src = b0; base = (long)bid * 8192; }
    else           { src = b1; base = (long)(bid - 128) * 8192; }
    float s = 0.f;
#pragma unroll
    for (int k = 0; k < 32; k++) { float v = __ldg(src + base + k * 256 + t); s += v * v; }
    red[t] = s; __syncthreads();
    for (int off = 128; off; off >>= 1) { if (t < off) red[t] += red[t + off]; __syncthreads(); }
    if (t == 0) d_part[bid] = red[0];
}

// ---------------- P2 (parallel, 6 blocks): bscale + Gram matrices --------------
__global__ __launch_bounds__(256) void k_prep(const float* __restrict__ W00,
                                              const float* __restrict__ W10,
                                              const float* __restrict__ W11,
                                              const float* __restrict__ g) {
    __shared__ float sw[9216];
    int blk = blockIdx.x, t = threadIdx.x;
    if (blk == 0 && t == 0) {
        float s0 = 0.f, s1 = 0.f;
        for (int i = 0; i < 128; i++) s0 += d_part[i];
        for (int i = 128; i < 192; i++) s1 += d_part[i];
        d_bscale[0] = __ldg(g) * rsqrtf(s0);
        d_bscale[1] = __ldg(g + 1) * rsqrtf(s1);
    }
    if (blk < 4) {
        for (int i = t; i < 2304; i += 256) sw[i] = __ldg(W00 + i);
        for (int i = t; i < 4608; i += 256) sw[2304 + i] = __ldg(W10 + i);
        __syncthreads();
        const float* s0 = sw;
        const float* s1 = sw + 2304;
        int e = blk * 256 + t;
        int n = e & 15, m = (e >> 4) & 15, c = (e >> 8) & 1, r = (e >> 9) & 1;
        float acc = 0.f;
        for (int o = 0; o < 16; o++) {
            const float* pm = s0 + (o * 16 + m) * 9;
            const float* pn = s0 + (o * 16 + n) * 9;
#pragma unroll
            for (int ij = 0; ij < 9; ij++) acc += pm[ij] * pn[ij];
        }
#pragma unroll
        for (int i1 = 0; i1 < 3; i1++) {
            if (((i1 + 1) & 1) != r) continue;
#pragma unroll
            for (int j1 = 0; j1 < 3; j1++) {
                if (((j1 + 1) & 1) != c) continue;
                int ij = i1 * 3 + j1;
                for (int o = 0; o < 32; o++)
                    acc += s1[(o * 16 + m) * 9 + ij] * s1[(o * 16 + n) * 9 + ij];
            }
        }
        d_blk0[e] = acc;
    } else {
        for (int i = t; i < 9216; i += 256) sw[i] = __ldg(W11 + i);
        __syncthreads();
        int e = (blk - 4) * 256 + t;
        int n = e & 15, m = (e >> 4) & 15, gg = e >> 8;
        float acc = 0.f;
        for (int o = 0; o < 32; o++) {
            const float* pm = sw + (o * 32 + gg * 16 + m) * 9;
            const float* pn = sw + (o * 32 + gg * 16 + n) * 9;
#pragma unroll
            for (int ij = 0; ij < 9; ij++) acc += pm[ij] * pn[ij];
        }
        d_blk1[e] = acc;
    }
}

// ---------------- Y0 = conv(x0, W00, s1, p2); dy-outer + ic prefetch ----------
__global__ __launch_bounds__(256, 2) void k_y0(const float* __restrict__ x0,
                                               const float* __restrict__ W00,
                                               int bbase) {
    extern __shared__ u64 sm[];
    int t = threadIdx.x;
    for (int idx = t; idx < 1152; idx += 256) {
        int ip = idx & 7, rest = idx >> 3, tap = rest % 9, ic = rest / 9;
        float wa = __ldg(W00 + ((2 * ip) * 16 + ic) * 9 + tap);
        float wb = __ldg(W00 + ((2 * ip + 1) * 16 + ic) * 9 + tap);
        sm[idx] = pk2(wa, wb);
    }
    __syncthreads();
    int b = bbase + blockIdx.z;
    int item = blockIdx.x * 256 + t;
    int r = item / 65, q = item - r * 65;
    int w0 = q * 4;
    bool valid = (r < 258);
    u64 acc[4][8];
#pragma unroll
    for (int p = 0; p < 4; p++)
#pragma unroll
        for (int ip = 0; ip < 8; ip++) acc[p][ip] = 0ull;
    const float* xb = x0 + (long)b * 1048576;
#pragma unroll 1
    for (int dy = 0; dy < 3; dy++) {
        int iy = r - 2 + dy;
        bool rowok = valid && iy >= 0 && iy < 256;
        const float* rowp = xb + iy * 256;
        float v[6];
#pragma unroll
        for (int j = 0; j < 6; j++) {
            int ix = w0 - 2 + j;
            v[j] = (rowok && ix >= 0 && ix < 256) ? __ldg(rowp + ix) : 0.f;
        }
#pragma unroll 1
        for (int ic = 0; ic < 16; ic++) {
            int icn = ic < 15 ? ic + 1 : ic;
            const float* nrow = xb + icn * 65536 + iy * 256;
            float nv[6];
#pragma unroll
            for (int j = 0; j < 6; j++) {
                int ix = w0 - 2 + j;
                nv[j] = (rowok && ix >= 0 && ix < 256) ? __ldg(nrow + ix) : 0.f;
            }
            const u64* wbase = sm + ic * 72 + dy * 24;
#pragma unroll
            for (int dx = 0; dx < 3; dx++) {
                u64 wr[8];
                ldw8(wbase + dx * 8, wr);
#pragma unroll
                for (int p = 0; p < 4; p++) {
                    u64 a = dup2(v[p + dx]);
#pragma unroll
                    for (int ip = 0; ip < 8; ip++) dfma(acc[p][ip], wr[ip], a);
                }
            }
#pragma unroll
            for (int j = 0; j < 6; j++) v[j] = nv[j];
        }
    }
    if (valid) {
        float* yb = d_Y0 + (long)b * 1065024 + r * 258 + w0;
        if (w0 + 4 <= 258) {
#pragma unroll
            for (int ip = 0; ip < 8; ip++) {
                float2 f0 = up2(acc[0][ip]), f1 = up2(acc[1][ip]), f2 = up2(acc[2][ip]), f3 = up2(acc[3][ip]);
                yb[(2 * ip) * 66564 + 0] = f0.x; yb[(2 * ip) * 66564 + 1] = f1.x;
                yb[(2 * ip) * 66564 + 2] = f2.x; yb[(2 * ip) * 66564 + 3] = f3.x;
                yb[(2 * ip + 1) * 66564 + 0] = f0.y; yb[(2 * ip + 1) * 66564 + 1] = f1.y;
                yb[(2 * ip + 1) * 66564 + 2] = f2.y; yb[(2 * ip + 1) * 66564 + 3] = f3.y;
            }
        } else {
#pragma unroll
            for (int p = 0; p < 4; p++) {
                if (w0 + p >= 258) break;
#pragma unroll
                for (int ip = 0; ip < 8; ip++) {
                    float2 f = up2(acc[p][ip]);
                    yb[(2 * ip) * 66564 + p] = f.x;
                    yb[(2 * ip + 1) * 66564 + p] = f.y;
                }
            }
        }
    }
}

// ------- Y1 = conv(x0,W10,s2,p3) + conv(x1,W11,s1,p2); ic prefetch ------------
__global__ __launch_bounds__(256, 2) void k_y1(const float* __restrict__ x0,
                                               const float* __restrict__ x1,
                                               const float* __restrict__ W10,
                                               const float* __restrict__ W11,
                                               int bbase) {
    extern __shared__ u64 sm[];
    u64* sA = sm; u64* sB2 = sm + 1152;
    int t = threadIdx.x;
    int half = blockIdx.z & 1, b = bbase + (blockIdx.z >> 1);
    for (int idx = t; idx < 1152; idx += 256) {
        int ip = idx & 7, rest = idx >> 3, tap = rest % 9, ic = rest / 9;
        float wa = __ldg(W10 + ((half * 16 + 2 * ip) * 16 + ic) * 9 + tap);
        float wb = __ldg(W10 + ((half * 16 + 2 * ip + 1) * 16 + ic) * 9 + tap);
        sA[idx] = pk2(wa, wb);
    }
    for (int idx = t; idx < 2304; idx += 256) {
        int ip = idx & 7, rest = idx >> 3, tap = rest % 9, ic = rest / 9;
        float wa = __ldg(W11 + ((half * 16 + 2 * ip) * 32 + ic) * 9 + tap);
        float wb = __ldg(W11 + ((half * 16 + 2 * ip + 1) * 32 + ic) * 9 + tap);
        sB2[idx] = pk2(wa, wb);
    }
    __syncthreads();
    int item = blockIdx.x * 256 + t;
    int u = item / 33, q = item - u * 33;
    int v0 = q * 4;
    bool valid = (u < 130);
    u64 acc[4][8];
#pragma unroll
    for (int p = 0; p < 4; p++)
#pragma unroll
        for (int ip = 0; ip < 8; ip++) acc[p][ip] = 0ull;
    const float* xa = x0 + (long)b * 1048576;
#pragma unroll 1
    for (int dy = 0; dy < 3; dy++) {
        int iy = 2 * u - 3 + dy;
        bool rowok = valid && iy >= 0 && iy < 256;
        const float* rowp = xa + iy * 256;
        float v[9];
#pragma unroll
        for (int j = 0; j < 9; j++) {
            int ix = 2 * v0 - 3 + j;
            v[j] = (rowok && ix >= 0 && ix < 256) ? __ldg(rowp + ix) : 0.f;
        }
#pragma unroll 1
        for (int ic = 0; ic < 16; ic++) {
            int icn = ic < 15 ? ic + 1 : ic;
            const float* nrow = xa + icn * 65536 + iy * 256;
            float nv[9];
#pragma unroll
            for (int j = 0; j < 9; j++) {
                int ix = 2 * v0 - 3 + j;
                nv[j] = (rowok && ix >= 0 && ix < 256) ? __ldg(nrow + ix) : 0.f;
            }
            const u64* wbase = sA + ic * 72 + dy * 24;
#pragma unroll
            for (int dx = 0; dx < 3; dx++) {
                u64 wr[8];
                ldw8(wbase + dx * 8, wr);
#pragma unroll
                for (int p = 0; p < 4; p++) {
                    u64 a = dup2(v[2 * p + dx]);
#pragma unroll
                    for (int ip = 0; ip < 8; ip++) dfma(acc[p][ip], wr[ip], a);
                }
            }
#pragma unroll
            for (int j = 0; j < 9; j++) v[j] = nv[j];
        }
    }
    const float* xb1 = x1 + (long)b * 524288;
#pragma unroll 1
    for (int dy = 0; dy < 3; dy++) {
        int iy = u - 2 + dy;
        bool rowok = valid && iy >= 0 && iy < 128;
        const float* rowp = xb1 + iy * 128;
        float v[6];
#pragma unroll
        for (int j = 0; j < 6; j++) {
            int ix = v0 - 2 + j;
            v[j] = (rowok && ix >= 0 && ix < 128) ? __ldg(rowp + ix) : 0.f;
        }
#pragma unroll 1
        for (int ic = 0; ic < 32; ic++) {
            int icn = ic < 31 ? ic + 1 : ic;
            const float* nrow = xb1 + icn * 16384 + iy * 128;
            float nv[6];
#pragma unroll
            for (int j = 0; j < 6; j++) {
                int ix = v0 - 2 + j;
                nv[j] = (rowok && ix >= 0 && ix < 128) ? __ldg(nrow + ix) : 0.f;
            }
            const u64* wbase = sB2 + ic * 72 + dy * 24;
#pragma unroll
            for (int dx = 0; dx < 3; dx++) {
                u64 wr[8];
                ldw8(wbase + dx * 8, wr);
#pragma unroll
                for (int p = 0; p < 4; p++) {
                    u64 a = dup2(v[p + dx]);
#pragma unroll
                    for (int ip = 0; ip < 8; ip++) dfma(acc[p][ip], wr[ip], a);
                }
            }
#pragma unroll
            for (int j = 0; j < 6; j++) v[j] = nv[j];
        }
    }
    if (valid) {
        float* yb = d_Y1 + (long)b * 540800 + (long)(half * 16) * 16900 + u * 130 + v0;
#pragma unroll
        for (int p = 0; p < 4; p++) {
            if (v0 + p >= 130) break;
#pragma unroll
            for (int ip = 0; ip < 8; ip++) {
                float2 f = up2(acc[p][ip]);
                yb[(2 * ip) * 16900 + p] = f.x;
                yb[(2 * ip + 1) * 16900 + p] = f.y;
            }
        }
    }
}

// ---- Z0: out0 = -convt(Y0,W00,s1,p2) - convt(Y1,W10,s2,p3,op1) + diag + bias --
__global__ __launch_bounds__(256, 2) void k_z0(const float* __restrict__ x0,
                                               const float* __restrict__ W00,
                                               const float* __restrict__ W10,
                                               const float* __restrict__ b0,
                                               float* __restrict__ out,
                                               int bbase) {
    extern __shared__ u64 sm[];
    u64* sW = sm; u64* sBk = sm + 1152; u64* sT = sm + 1664;
    int t = threadIdx.x;
    for (int idx = t; idx < 1152; idx += 256) {
        int ip = idx & 7, rest = idx >> 3, tap = rest % 9, o = rest / 9;
        float wa = -__ldg(W00 + (o * 16 + 2 * ip) * 9 + tap);
        float wb = -__ldg(W00 + (o * 16 + 2 * ip + 1) * 9 + tap);
        sW[idx] = pk2(wa, wb);
    }
    for (int idx = t; idx < 512; idx += 256) {
        int ip = idx & 7, n = (idx >> 3) & 15, rc = idx >> 7;
        float a0 = d_blk0[(rc * 16 + 2 * ip) * 16 + n];
        float a1 = d_blk0[(rc * 16 + 2 * ip + 1) * 16 + n];
        sBk[idx] = pk2(a0, a1);
    }
    for (int idx = t; idx < 2304; idx += 256) {
        int ip = idx & 7, rest = idx >> 3, o = rest & 31, tap = rest >> 5;
        float wa = -__ldg(W10 + (o * 16 + 2 * ip) * 9 + tap);
        float wb = -__ldg(W10 + (o * 16 + 2 * ip + 1) * 9 + tap);
        sT[idx] = pk2(wa, wb);
    }
    __syncthreads();
    int b = bbase + blockIdx.z, lane = t & 31, warp = t >> 5;
    int h = blockIdx.y * 8 + warp;
    int w0 = (blockIdx.x * 32 + lane) * 4;
    u64 acc[4][8];
#pragma unroll
    for (int p = 0; p < 4; p++)
#pragma unroll
        for (int ip = 0; ip < 8; ip++) acc[p][ip] = 0ull;

    // term1: -convt(Y0,W00); rr-outer, o-inner with row prefetch
    const float* yb = d_Y0 + (long)b * 1065024 + h * 258 + w0;
#pragma unroll 1
    for (int rr = 0; rr < 3; rr++) {
        int dy = 2 - rr;
        const float* yr = yb + rr * 258;
        float2 A0 = *(const float2*)yr;
        float2 A1 = *(const float2*)(yr + 2);
        float2 A2 = *(const float2*)(yr + 4);
#pragma unroll 1
        for (int o = 0; o < 16; o++) {
            int on = o < 15 ? o + 1 : o;
            const float* nr = yr + on * 66564;
            float2 N0 = *(const float2*)nr;
            float2 N1 = *(const float2*)(nr + 2);
            float2 N2 = *(const float2*)(nr + 4);
            float v[6] = {A0.x, A0.y, A1.x, A1.y, A2.x, A2.y};
            const u64* wbase = sW + o * 72 + dy * 24;
#pragma unroll
            for (int dx = 0; dx < 3; dx++) {
                u64 wr[8];
                ldw8(wbase + dx * 8, wr);
#pragma unroll
                for (int p = 0; p < 4; p++) {
                    u64 a = dup2(v[p + 2 - dx]);
#pragma unroll
                    for (int ip = 0; ip < 8; ip++) dfma(acc[p][ip], wr[ip], a);
                }
            }
            A0 = N0; A1 = N1; A2 = N2;
        }
    }
    // term2: -convt(Y1,W10,s2,p3,op1); per-o tap prefetch
    {
        int qc = (w0 >> 1) + 1;
        int hp = h & 1;
        int ntap = hp ? 2 : 1;
        int dy0 = hp ? 0 : 1;
        int qr0 = hp ? ((h + 3) >> 1) : ((h >> 1) + 1);
        int qr1 = (h + 1) >> 1;
        const float* y1b = d_Y1 + (long)b * 540800 + qc;
        float c0A, c0B, c0C, c1A = 0.f, c1B = 0.f, c1C = 0.f;
        {
            const float* yr = y1b + qr0 * 130;
            c0A = __ldg(yr); c0B = __ldg(yr + 1); c0C = __ldg(yr + 2);
            if (ntap == 2) {
                const float* ys = y1b + qr1 * 130;
                c1A = __ldg(ys); c1B = __ldg(ys + 1); c1C = __ldg(ys + 2);
            }
        }
#pragma unroll 1
        for (int o = 0; o < 32; o++) {
            int on = o < 31 ? o + 1 : o;
            float n0A, n0B, n0C, n1A = 0.f, n1B = 0.f, n1C = 0.f;
            {
                const float* yr = y1b + on * 16900 + qr0 * 130;
                n0A = __ldg(yr); n0B = __ldg(yr + 1); n0C = __ldg(yr + 2);
                if (ntap == 2) {
                    const float* ys = y1b + on * 16900 + qr1 * 130;
                    n1A = __ldg(ys); n1B = __ldg(ys + 1); n1C = __ldg(ys + 2);
                }
            }
            {
                u64 aA = dup2(c0A), aB = dup2(c0B), aC = dup2(c0C);
                u64 wr[8];
                ldw8(sT + ((dy0 * 3 + 0) * 32 + o) * 8, wr);
#pragma unroll
                for (int ip = 0; ip < 8; ip++) { dfma(acc[1][ip], wr[ip], aB); dfma(acc[3][ip], wr[ip], aC); }
                ldw8(sT + ((dy0 * 3 + 1) * 32 + o) * 8, wr);
#pragma unroll
                for (int ip = 0; ip < 8; ip++) { dfma(acc[0][ip], wr[ip], aA); dfma(acc[2][ip], wr[ip], aB); }
                ldw8(sT + ((dy0 * 3 + 2) * 32 + o) * 8, wr);
#pragma unroll
                for (int ip = 0; ip < 8; ip++) { dfma(acc[1][ip], wr[ip], aA); dfma(acc[3][ip], wr[ip], aB); }
            }
            if (ntap == 2) {
                u64 aA = dup2(c1A), aB = dup2(c1B), aC = dup2(c1C);
                u64 wr[8];
                ldw8(sT + ((2 * 3 + 0) * 32 + o) * 8, wr);
#pragma unroll
                for (int ip = 0; ip < 8; ip++) { dfma(acc[1][ip], wr[ip], aB); dfma(acc[3][ip], wr[ip], aC); }
                ldw8(sT + ((2 * 3 + 1) * 32 + o) * 8, wr);
#pragma unroll
                for (int ip = 0; ip < 8; ip++) { dfma(acc[0][ip], wr[ip], aA); dfma(acc[2][ip], wr[ip], aB); }
                ldw8(sT + ((2 * 3 + 2) * 32 + o) * 8, wr);
#pragma unroll
                for (int ip = 0; ip < 8; ip++) { dfma(acc[1][ip], wr[ip], aA); dfma(acc[3][ip], wr[ip], aB); }
            }
            c0A = n0A; c0B = n0B; c0C = n0C;
            c1A = n1A; c1B = n1B; c1C = n1C;
        }
    }
    // term3: +diag with n prefetch
    {
        int r = h & 1;
        const u64* sb0 = sBk + (r * 2 + 0) * 128;
        const u64* sb1 = sBk + (r * 2 + 1) * 128;
        const float* xq = x0 + (long)b * 1048576 + h * 256 + w0;
        float4 xv = *(const float4*)xq;
#pragma unroll 1
        for (int n = 0; n < 16; n++) {
            int nn = n < 15 ? n + 1 : n;
            float4 nx = *(const float4*)(xq + nn * 65536);
            u64 a0 = dup2(xv.x), a1 = dup2(xv.y), a2 = dup2(xv.z), a3 = dup2(xv.w);
            u64 e[8], od[8];
            ldw8(sb0 + n * 8, e);
            ldw8(sb1 + n * 8, od);
#pragma unroll
            for (int ip = 0; ip < 8; ip++) {
                dfma(acc[0][ip], e[ip], a0);
                dfma(acc[1][ip], od[ip], a1);
                dfma(acc[2][ip], e[ip], a2);
                dfma(acc[3][ip], od[ip], a3);
            }
            xv = nx;
        }
    }
    float bs = d_bscale[0];
    const float* bb = b0 + h * 256 + w0;
    float* ob = out + (long)b * 1048576 + h * 256 + w0;
#pragma unroll
    for (int ip = 0; ip < 8; ip++) {
        float2 f0 = up2(acc[0][ip]), f1 = up2(acc[1][ip]), f2 = up2(acc[2][ip]), f3 = up2(acc[3][ip]);
        float4 bv0 = *reinterpret_cast<const float4*>(bb + (2 * ip) * 65536);
        float4 bv1 = *reinterpret_cast<const float4*>(bb + (2 * ip + 1) * 65536);
        *(float4*)(ob + (2 * ip) * 65536) =
            make_float4(fmaf(bs, bv0.x, f0.x), fmaf(bs, bv0.y, f1.x),
                        fmaf(bs, bv0.z, f2.x), fmaf(bs, bv0.w, f3.x));
        *(float4*)(ob + (2 * ip + 1) * 65536) =
            make_float4(fmaf(bs, bv1.x, f0.y), fmaf(bs, bv1.y, f1.y),
                        fmaf(bs, bv1.z, f2.y), fmaf(bs, bv1.w, f3.y));
    }
}

// -------- Z1: out1 = -convt(Y1,W11,s1,p2) + diag(blk1,x1) + bias ---------------
__global__ __launch_bounds__(256, 2) void k_z1(const float* __restrict__ x1,
                                               const float* __restrict__ W11,
                                               const float* __restrict__ b1,
                                               float* __restrict__ out1,
                                               int bbase) {
    extern __shared__ u64 sm[];
    u64* sW = sm; u64* sB = sm + 2304;
    int t = threadIdx.x;
    int half = blockIdx.z & 1, b = bbase + (blockIdx.z >> 1);
    for (int idx = t; idx < 2304; idx += 256) {
        int ip = idx & 7, rest = idx >> 3, tap = rest % 9, o = rest / 9;
        float wa = -__ldg(W11 + (o * 32 + half * 16 + 2 * ip) * 9 + tap);
        float wb = -__ldg(W11 + (o * 32 + half * 16 + 2 * ip + 1) * 9 + tap);
        sW[idx] = pk2(wa, wb);
    }
    for (int idx = t; idx < 128; idx += 256) {
        int ip = idx & 7, n = idx >> 3;
        float a0 = d_blk1[half * 256 + (2 * ip) * 16 + n];
        float a1 = d_blk1[half * 256 + (2 * ip + 1) * 16 + n];
        sB[idx] = pk2(a0, a1);
    }
    __syncthreads();
    int lane = t & 31, warp = t >> 5;
    int h = blockIdx.y * 8 + warp;
    int w0 = lane * 4;
    u64 acc[4][8];
#pragma unroll
    for (int p = 0; p < 4; p++)
#pragma unroll
        for (int ip = 0; ip < 8; ip++) acc[p][ip] = 0ull;
    // rr-outer, o-inner with row prefetch
    const float* yb = d_Y1 + (long)b * 540800 + h * 130 + w0;
#pragma unroll 1
    for (int rr = 0; rr < 3; rr++) {
        int dy = 2 - rr;
        const float* yr = yb + rr * 130;
        float2 A0 = *(const float2*)yr;
        float2 A1 = *(const float2*)(yr + 2);
        float2 A2 = *(const float2*)(yr + 4);
#pragma unroll 1
        for (int o = 0; o < 32; o++) {
            int on = o < 31 ? o + 1 : o;
            const float* nr = yr + on * 16900;
            float2 N0 = *(const float2*)nr;
            float2 N1 = *(const float2*)(nr + 2);
            float2 N2 = *(const float2*)(nr + 4);
            float v[6] = {A0.x, A0.y, A1.x, A1.y, A2.x, A2.y};
            const u64* wbase = sW + o * 72 + dy * 24;
#pragma unroll
            for (int dx = 0; dx < 3; dx++) {
                u64 wr[8];
                ldw8(wbase + dx * 8, wr);
#pragma unroll
                for (int p = 0; p < 4; p++) {
                    u64 a = dup2(v[p + 2 - dx]);
#pragma unroll
                    for (int ip = 0; ip < 8; ip++) dfma(acc[p][ip], wr[ip], a);
                }
            }
            A0 = N0; A1 = N1; A2 = N2;
        }
    }
    // diag with n prefetch
    {
        const float* xq = x1 + (long)b * 524288 + (long)(half * 16) * 16384 + h * 128 + w0;
        float4 xv = *(const float4*)xq;
#pragma unroll 1
        for (int n = 0; n < 16; n++) {
            int nn = n < 15 ? n + 1 : n;
            float4 nx = *(const float4*)(xq + nn * 16384);
            u64 a0 = dup2(xv.x), a1 = dup2(xv.y), a2 = dup2(xv.z), a3 = dup2(xv.w);
            u64 e[8];
            ldw8(sB + n * 8, e);
#pragma unroll
            for (int ip = 0; ip < 8; ip++) {
                dfma(acc[0][ip], e[ip], a0);
                dfma(acc[1][ip], e[ip], a1);
                dfma(acc[2][ip], e[ip], a2);
                dfma(acc[3][ip], e[ip], a3);
            }
            xv = nx;
        }
    }
    float bs = d_bscale[1];
    const float* bb = b1 + (long)(half * 16) * 16384 + h * 128 + w0;
    float* ob = out1 + (long)b * 524288 + (long)(half * 16) * 16384 + h * 128 + w0;
#pragma unroll
    for (int ip = 0; ip < 8; ip++) {
        float2 f0 = up2(acc[0][ip]), f1 = up2(acc[1][ip]), f2 = up2(acc[2][ip]), f3 = up2(acc[3][ip]);
        float4 bv0 = *reinterpret_cast<const float4*>(bb + (2 * ip) * 16384);
        float4 bv1 = *reinterpret_cast<const float4*>(bb + (2 * ip + 1) * 16384);
        *(float4*)(ob + (2 * ip) * 16384) =
            make_float4(fmaf(bs, bv0.x, f0.x), fmaf(bs, bv0.y, f1.x),
                        fmaf(bs, bv0.z, f2.x), fmaf(bs, bv0.w, f3.x));
        *(float4*)(ob + (2 * ip + 1) * 16384) =
            make_float4(fmaf(bs, bv1.x, f0.y), fmaf(bs, bv1.y, f1.y),
                        fmaf(bs, bv1.z, f2.y), fmaf(bs, bv1.w, f3.y));
    }
}

// ------- launch: two STAGGERED batch pipelines + prep branch (2 extra streams) --
extern "C" void kernel_launch(void* const* d_in, const int* in_sizes, int n_in,
                              void* d_out, int out_size) {
    const float* x0  = (const float*)d_in[0];
    const float* x1  = (const float*)d_in[1];
    const float* W00 = (const float*)d_in[2];
    const float* W10 = (const float*)d_in[3];
    const float* W11 = (const float*)d_in[4];
    const float* b0  = (const float*)d_in[5];
    const float* b1  = (const float*)d_in[6];
    const float* g   = (const float*)d_in[7];
    float* out0 = (float*)d_out;
    float* out1 = out0 + (long)16 * 16 * 256 * 256;

    static cudaStream_t sPrep = nullptr, sP1 = nullptr;
    static cudaEvent_t eFork = nullptr, ePrep = nullptr, eP1 = nullptr;
    if (sPrep == nullptr) {
        cudaStreamCreateWithFlags(&sPrep, cudaStreamNonBlocking);
        cudaStreamCreateWithFlags(&sP1, cudaStreamNonBlocking);
        cudaEventCreateWithFlags(&eFork, cudaEventDisableTiming);
        cudaEventCreateWithFlags(&ePrep, cudaEventDisableTiming);
        cudaEventCreateWithFlags(&eP1, cudaEventDisableTiming);
    }

    cudaEventRecord(eFork, 0);
    cudaStreamWaitEvent(sPrep, eFork, 0);
    cudaStreamWaitEvent(sP1, eFork, 0);

    // prep branch
    k_ssq<<<192, 256, 0, sPrep>>>(b0, b1);
    k_prep<<<6, 256, 0, sPrep>>>(W00, W10, W11, g);
    cudaEventRecord(ePrep, sPrep);

    // pipeline A (origin stream): batches 0..7, order y1, y0, z1, z0
    k_y1<<<dim3(17, 1, 16), 256, 3456 * 8>>>(x0, x1, W10, W11, 0);
    k_y0<<<dim3(66, 1, 8), 256, 1152 * 8>>>(x0, W00, 0);
    cudaStreamWaitEvent(0, ePrep, 0);
    k_z1<<<dim3(1, 16, 16), 256, 2432 * 8>>>(x1, W11, b1, out1, 0);
    k_z0<<<dim3(2, 32, 8), 256, 3968 * 8>>>(x0, W00, W10, b0, out0, 0);

    // pipeline B (sP1): batches 8..15, REVERSED order y0, y1, z0, z1
    k_y0<<<dim3(66, 1, 8), 256, 1152 * 8, sP1>>>(x0, W00, 8);
    k_y1<<<dim3(17, 1, 16), 256, 3456 * 8, sP1>>>(x0, x1, W10, W11, 8);
    cudaStreamWaitEvent(sP1, ePrep, 0);
    k_z0<<<dim3(2, 32, 8), 256, 3968 * 8, sP1>>>(x0, W00, W10, b0, out0, 8);
    k_z1<<<dim3(1, 16, 16), 256, 2432 * 8, sP1>>>(x1, W11, b1, out1, 8);
    cudaEventRecord(eP1, sP1);

    // join
    cudaStreamWaitEvent(0, eP1, 0);
}